// round 6
// baseline (speedup 1.0000x reference)
#include <cuda_runtime.h>
#include <cuda_bf16.h>
#include <cstdint>

#define B_   8
#define S_   4096
#define D_HD 64
#define BQ   128
#define BK   128
#define NTH  512

// ---- pipelined smem: 2 stages x 4 tiles(18432B each: khi,klo,vhi,vlo) ----
#define STAGE_BYTES 73728
#define OFF_KHI 0
#define OFF_KLO 18432
#define OFF_VHI 36864
#define OFF_VLO 55296
#define SM_QHI  147456          // persistent Q hi tile [128 x 144B]
#define SM_QLO  165888
#define SM_RS   184320          // float[2][128]
#define SM_TOT  185344

// pre-split K/V in tile-ready layout: [b*S + row][72 halves] (144B row stride)
#define GROW 72
__device__ __align__(16) __nv_bfloat16 g_khi[(size_t)B_ * S_ * GROW];
__device__ __align__(16) __nv_bfloat16 g_klo[(size_t)B_ * S_ * GROW];
__device__ __align__(16) __nv_bfloat16 g_vhi[(size_t)B_ * S_ * GROW];
__device__ __align__(16) __nv_bfloat16 g_vlo[(size_t)B_ * S_ * GROW];
__device__ float g_rowsum[(size_t)B_ * S_];

static __device__ __forceinline__ uint32_t smem_u32(const void* p) {
    uint32_t a;
    asm("{ .reg .u64 t; cvta.to.shared.u64 t, %1; cvt.u32.u64 %0, t; }" : "=r"(a) : "l"(p));
    return a;
}
static __device__ __forceinline__ void ldsm4(uint32_t* r, uint32_t addr) {
    asm volatile("ldmatrix.sync.aligned.m8n8.x4.shared.b16 {%0,%1,%2,%3}, [%4];"
                 : "=r"(r[0]), "=r"(r[1]), "=r"(r[2]), "=r"(r[3]) : "r"(addr));
}
static __device__ __forceinline__ void ldsm4t(uint32_t* r, uint32_t addr) {
    asm volatile("ldmatrix.sync.aligned.m8n8.x4.trans.shared.b16 {%0,%1,%2,%3}, [%4];"
                 : "=r"(r[0]), "=r"(r[1]), "=r"(r[2]), "=r"(r[3]) : "r"(addr));
}
static __device__ __forceinline__ void mma_bf16(float* c, const uint32_t* a,
                                                uint32_t b0, uint32_t b1) {
    asm volatile("mma.sync.aligned.m16n8k16.row.col.f32.bf16.bf16.f32 "
                 "{%0,%1,%2,%3}, {%4,%5,%6,%7}, {%8,%9}, {%0,%1,%2,%3};"
                 : "+f"(c[0]), "+f"(c[1]), "+f"(c[2]), "+f"(c[3])
                 : "r"(a[0]), "r"(a[1]), "r"(a[2]), "r"(a[3]), "r"(b0), "r"(b1));
}
static __device__ __forceinline__ uint32_t packbf(float a, float b) {
    __nv_bfloat162 t = __floats2bfloat162_rn(a, b);
    return *reinterpret_cast<uint32_t*>(&t);
}
static __device__ __forceinline__ float bfhi(float x) {
    return __bfloat162float(__float2bfloat16_rn(x));
}

// ---- one-time split of K/V into tile-ready bf16 hi/lo gmem ----
__global__ __launch_bounds__(256)
void prep_split_kernel(const float* __restrict__ K, const float* __restrict__ V)
{
    size_t idx = (size_t)blockIdx.x * 256 + threadIdx.x;   // float4 index
    size_t row = idx >> 4;
    int d4 = (int)(idx & 15);
    size_t dst = row * GROW + (size_t)d4 * 4;

    float4 kv = reinterpret_cast<const float4*>(K)[idx];
    float h0 = bfhi(kv.x), h1 = bfhi(kv.y), h2 = bfhi(kv.z), h3 = bfhi(kv.w);
    *reinterpret_cast<uint2*>(&g_khi[dst]) = make_uint2(packbf(h0, h1), packbf(h2, h3));
    *reinterpret_cast<uint2*>(&g_klo[dst]) =
        make_uint2(packbf(kv.x - h0, kv.y - h1), packbf(kv.z - h2, kv.w - h3));

    float4 vv = reinterpret_cast<const float4*>(V)[idx];
    float g0 = bfhi(vv.x), g1 = bfhi(vv.y), g2 = bfhi(vv.z), g3 = bfhi(vv.w);
    *reinterpret_cast<uint2*>(&g_vhi[dst]) = make_uint2(packbf(g0, g1), packbf(g2, g3));
    *reinterpret_cast<uint2*>(&g_vlo[dst]) =
        make_uint2(packbf(vv.x - g0, vv.y - g1), packbf(vv.z - g2, vv.w - g3));
}

__global__ __launch_bounds__(NTH, 1)
void attn_hmma_kernel(const float* __restrict__ Q,
                      const int*   __restrict__ mask,
                      float* __restrict__ ctx_out,
                      float* __restrict__ attn_out)
{
    extern __shared__ char smc[];
    const uint32_t sb = smem_u32(smc);

    const int tid  = threadIdx.x;
    const int w    = tid >> 5;
    const int lane = tid & 31;
    const int lrow = lane & 7;
    const int lsub = lane >> 3;
    const int wq   = w >> 1;          // q-row group: rows [16wq, 16wq+16)
    const int h    = w & 1;           // column half: cols [64h, 64h+64)
    const int b    = blockIdx.y;
    const int q0   = blockIdx.x * BQ;

    // ldmatrix lane-offsets (bytes within a tile, 144B row stride)
    const uint32_t kofsB = (uint32_t)((((lsub & 2) ? 8 : 0) + lrow) * 144 + ((lsub & 1) ? 16 : 0));
    const uint32_t kofsA = (uint32_t)((lrow + ((lsub & 1) ? 8 : 0)) * 144 + ((lsub & 2) ? 16 : 0));

    // async copy of one k-tile (4 sub-tiles of 18432B = 1152 x 16B) into a stage
    auto issue_copy = [&](int t, int buf) {
        size_t gbase = ((size_t)b * S_ + (size_t)t * BK) * GROW;
        const __nv_bfloat16* gp[4] = { g_khi + gbase, g_klo + gbase,
                                       g_vhi + gbase, g_vlo + gbase };
        uint32_t s0 = sb + (uint32_t)buf * STAGE_BYTES;
        #pragma unroll
        for (int a = 0; a < 4; ++a) {
            uint64_t ga = (uint64_t)__cvta_generic_to_global(gp[a]);
            uint32_t sa = s0 + (uint32_t)a * 18432u;
            #pragma unroll
            for (int i = 0; i < 2; ++i) {
                uint32_t o = (uint32_t)(tid + i * NTH) * 16u;
                asm volatile("cp.async.cg.shared.global [%0], [%1], 16;"
                             :: "r"(sa + o), "l"(ga + o));
            }
            if (tid < 128) {
                uint32_t o = (uint32_t)(1024 + tid) * 16u;
                asm volatile("cp.async.cg.shared.global [%0], [%1], 16;"
                             :: "r"(sa + o), "l"(ga + o));
            }
        }
        asm volatile("cp.async.commit_group;" ::: "memory");
    };

    // prologue: start tile 0; split Q (scaled 1/8) into persistent smem tiles
    issue_copy(0, 0);
    {
        const float* Qg = Q + ((size_t)b * S_ + q0) * D_HD;
        #pragma unroll
        for (int it = 0; it < 4; ++it) {
            int idx = (it * NTH + tid) * 4;
            int q = idx >> 6, d = idx & 63;
            float4 v = *reinterpret_cast<const float4*>(Qg + idx);
            float x0 = v.x * 0.125f, x1 = v.y * 0.125f, x2 = v.z * 0.125f, x3 = v.w * 0.125f;
            float h0 = bfhi(x0), h1 = bfhi(x1), h2 = bfhi(x2), h3 = bfhi(x3);
            uint32_t off = (uint32_t)(q * 144 + d * 2);
            *reinterpret_cast<uint32_t*>(smc + SM_QHI + off)     = packbf(h0, h1);
            *reinterpret_cast<uint32_t*>(smc + SM_QHI + off + 4) = packbf(h2, h3);
            *reinterpret_cast<uint32_t*>(smc + SM_QLO + off)     = packbf(x0 - h0, x1 - h1);
            *reinterpret_cast<uint32_t*>(smc + SM_QLO + off + 4) = packbf(x2 - h2, x3 - h3);
        }
    }

    float ctx[8][4];
    #pragma unroll
    for (int i = 0; i < 8; ++i)
        #pragma unroll
        for (int j = 0; j < 4; ++j) ctx[i][j] = 0.0f;
    float rs0 = 0.0f, rs1 = 0.0f;

    const size_t rowA = (size_t)b * S_ + q0 + 16 * wq + (lane >> 2);
    const int    colL = 2 * (lane & 3);
    const uint32_t aHI = sb + SM_QHI + (uint32_t)(wq * 2304) + kofsA;
    const uint32_t aLO = sb + SM_QLO + (uint32_t)(wq * 2304) + kofsA;

    for (int t = 0; t < S_ / BK; ++t) {
        const int buf = t & 1;
        const int k0  = t << 7;

        asm volatile("cp.async.wait_group 0;" ::: "memory");
        __syncthreads();                       // tile t resident (incl. Q on t=0)
        if (t + 1 < S_ / BK) issue_copy(t + 1, (t + 1) & 1);

        const uint32_t base = sb + (uint32_t)buf * STAGE_BYTES;

        // ---- QK^T (this warp's 64-col half): 3 bf16 passes ----
        float sc[8][4];
        #pragma unroll
        for (int i = 0; i < 8; ++i)
            #pragma unroll
            for (int j = 0; j < 4; ++j) sc[i][j] = 0.0f;

        #pragma unroll
        for (int pass = 0; pass < 3; ++pass) {
            const uint32_t abase = (pass == 2) ? aLO : aHI;
            const uint32_t bbase = base + ((pass == 1) ? OFF_KLO : OFF_KHI)
                                 + (uint32_t)(h * 9216) + kofsB;
            #pragma unroll
            for (int kc = 0; kc < 4; ++kc) {
                uint32_t af[4];
                ldsm4(af, abase + (uint32_t)(kc * 32));
                #pragma unroll
                for (int ntp = 0; ntp < 4; ++ntp) {
                    uint32_t bfr[4];
                    ldsm4(bfr, bbase + (uint32_t)(ntp * 2304 + kc * 32));
                    mma_bf16(sc[2 * ntp],     af, bfr[0], bfr[1]);
                    mma_bf16(sc[2 * ntp + 1], af, bfr[2], bfr[3]);
                }
            }
        }

        // ---- mask + exp + direct attn write ----
        #pragma unroll
        for (int nt = 0; nt < 8; ++nt) {
            const size_t cg = (size_t)(k0 + h * 64 + nt * 8 + colL);
            const int2 m0 = *reinterpret_cast<const int2*>(mask + rowA * S_ + cg);
            const int2 m1 = *reinterpret_cast<const int2*>(mask + (rowA + 8) * S_ + cg);
            float e0 = m0.x ? 0.0f : __expf(sc[nt][0]);
            float e1 = m0.y ? 0.0f : __expf(sc[nt][1]);
            float e2 = m1.x ? 0.0f : __expf(sc[nt][2]);
            float e3 = m1.y ? 0.0f : __expf(sc[nt][3]);
            rs0 += e0 + e1; rs1 += e2 + e3;
            *reinterpret_cast<float2*>(attn_out + rowA * S_ + cg)       = make_float2(e0, e1);
            *reinterpret_cast<float2*>(attn_out + (rowA + 8) * S_ + cg) = make_float2(e2, e3);
            sc[nt][0] = e0; sc[nt][1] = e1; sc[nt][2] = e2; sc[nt][3] = e3;
        }

        const uint32_t vhb = base + OFF_VHI + (uint32_t)(h * 9216) + kofsA;
        const uint32_t vlb = base + OFF_VLO + (uint32_t)(h * 9216) + kofsA;

        // ---- phase 1: Ph*Vh + Ph*Vl (only ph live) ----
        uint32_t ph[4][4];
        #pragma unroll
        for (int kcp = 0; kcp < 4; ++kcp) {
            #pragma unroll
            for (int f = 0; f < 4; ++f) {
                const float* s = sc[2 * kcp + ((f & 2) ? 1 : 0)];
                float x = s[(f & 1) ? 2 : 0], y = s[(f & 1) ? 3 : 1];
                ph[kcp][f] = packbf(bfhi(x), bfhi(y));
            }
        }
        #pragma unroll
        for (int kcp = 0; kcp < 4; ++kcp) {
            uint32_t vf[4];
            #pragma unroll
            for (int ntp = 0; ntp < 4; ++ntp) {
                ldsm4t(vf, vhb + (uint32_t)(kcp * 2304 + ntp * 32));
                mma_bf16(ctx[2 * ntp],     ph[kcp], vf[0], vf[1]);
                mma_bf16(ctx[2 * ntp + 1], ph[kcp], vf[2], vf[3]);
            }
            #pragma unroll
            for (int ntp = 0; ntp < 4; ++ntp) {
                ldsm4t(vf, vlb + (uint32_t)(kcp * 2304 + ntp * 32));
                mma_bf16(ctx[2 * ntp],     ph[kcp], vf[0], vf[1]);
                mma_bf16(ctx[2 * ntp + 1], ph[kcp], vf[2], vf[3]);
            }
        }

        // ---- phase 2: Pl*Vh (sc retired chunk by chunk) ----
        #pragma unroll
        for (int kcp = 0; kcp < 4; ++kcp) {
            uint32_t pl[4];
            #pragma unroll
            for (int f = 0; f < 4; ++f) {
                const float* s = sc[2 * kcp + ((f & 2) ? 1 : 0)];
                float x = s[(f & 1) ? 2 : 0], y = s[(f & 1) ? 3 : 1];
                pl[f] = packbf(x - bfhi(x), y - bfhi(y));
            }
            uint32_t vf[4];
            #pragma unroll
            for (int ntp = 0; ntp < 4; ++ntp) {
                ldsm4t(vf, vhb + (uint32_t)(kcp * 2304 + ntp * 32));
                mma_bf16(ctx[2 * ntp],     pl, vf[0], vf[1]);
                mma_bf16(ctx[2 * ntp + 1], pl, vf[2], vf[3]);
            }
        }
    }

    // ---- rowsums (per half) + cross-half ctx combine ----
    rs0 += __shfl_xor_sync(0xffffffffu, rs0, 1);
    rs0 += __shfl_xor_sync(0xffffffffu, rs0, 2);
    rs1 += __shfl_xor_sync(0xffffffffu, rs1, 1);
    rs1 += __shfl_xor_sync(0xffffffffu, rs1, 2);

    float* rsum = reinterpret_cast<float*>(smc + SM_RS);    // [2][128]
    float* cbuf = reinterpret_cast<float*>(smc);            // reuse stage0: [128][68]
    const int r = 16 * wq + (lane >> 2);
    __syncthreads();   // all warps done with stage buffers
    if ((lane & 3) == 0) {
        rsum[h * 128 + r]     = rs0;
        rsum[h * 128 + r + 8] = rs1;
    }
    if (h == 1) {
        #pragma unroll
        for (int nt = 0; nt < 8; ++nt) {
            int d = nt * 8 + colL;
            *reinterpret_cast<float2*>(cbuf + r * 68 + d) =
                make_float2(ctx[nt][0], ctx[nt][1]);
            *reinterpret_cast<float2*>(cbuf + (r + 8) * 68 + d) =
                make_float2(ctx[nt][2], ctx[nt][3]);
        }
    }
    __syncthreads();
    if (tid < BQ) g_rowsum[(size_t)b * S_ + q0 + tid] = rsum[tid] + rsum[128 + tid];

    if (h == 0) {
        const float inv0 = 1.0f / (rsum[r] + rsum[128 + r]);
        const float inv1 = 1.0f / (rsum[r + 8] + rsum[128 + r + 8]);
        #pragma unroll
        for (int nt = 0; nt < 8; ++nt) {
            int d = nt * 8 + colL;
            float2 o0 = *reinterpret_cast<const float2*>(cbuf + r * 68 + d);
            float2 o1 = *reinterpret_cast<const float2*>(cbuf + (r + 8) * 68 + d);
            *reinterpret_cast<float2*>(ctx_out + rowA * D_HD + d) =
                make_float2((ctx[nt][0] + o0.x) * inv0, (ctx[nt][1] + o0.y) * inv0);
            *reinterpret_cast<float2*>(ctx_out + (rowA + 8) * D_HD + d) =
                make_float2((ctx[nt][2] + o1.x) * inv1, (ctx[nt][3] + o1.y) * inv1);
        }
    }
}

__global__ void attn_norm_kernel(float* __restrict__ attn)
{
    const size_t n4 = (size_t)B_ * S_ * S_ / 4;
    for (size_t i = (size_t)blockIdx.x * blockDim.x + threadIdx.x;
         i < n4; i += (size_t)gridDim.x * blockDim.x) {
        float4 v = reinterpret_cast<const float4*>(attn)[i];
        size_t row = i >> 10;
        float s = __fdividef(1.0f, g_rowsum[row]);
        v.x *= s; v.y *= s; v.z *= s; v.w *= s;
        reinterpret_cast<float4*>(attn)[i] = v;
    }
}

extern "C" void kernel_launch(void* const* d_in, const int* in_sizes, int n_in,
                              void* d_out, int out_size)
{
    const float* Q = (const float*)d_in[0];
    const float* K = (const float*)d_in[1];
    const float* V = (const float*)d_in[2];
    const int* mask = (const int*)d_in[3];

    float* ctx_out  = (float*)d_out;
    float* attn_out = ctx_out + (size_t)B_ * S_ * D_HD;

    static bool attr_set = false;
    if (!attr_set) {
        cudaFuncSetAttribute(attn_hmma_kernel,
                             cudaFuncAttributeMaxDynamicSharedMemorySize, SM_TOT);
        attr_set = true;
    }

    prep_split_kernel<<<(B_ * S_ * D_HD / 4) / 256, 256>>>(K, V);
    dim3 grid(S_ / BQ, B_);
    attn_hmma_kernel<<<grid, NTH, SM_TOT>>>(Q, mask, ctx_out, attn_out);
    attn_norm_kernel<<<8192, 256>>>(attn_out);
}

// round 7
// speedup vs baseline: 1.5216x; 1.5216x over previous
#include <cuda_runtime.h>
#include <cuda_fp16.h>
#include <cstdint>

#define B_   8
#define S_   4096
#define D_HD 64
#define BQ   128
#define BK   128
#define NTH  256

// ---- 3-stage pipelined smem: stage = KF(18432) + VF(18432) ----
#define STAGE_BYTES 36864
#define OFF_KF 0
#define OFF_VF 18432
#define SM_Q   110592          // transient Q fp32 staging (uses stage-2 slot first)
#define SM_RS  110592          // after prologue, stage2 belongs to pipeline; RS separate:
#undef SM_RS
#define SM_RS  (3 * STAGE_BYTES)        // float[128]
#define SM_TOT (3 * STAGE_BYTES + 512)
#define QS_STRIDE 68

// fp16 K/V in tile-ready layout: [b*S + row][72 halves] (144B row stride)
#define GROW 72
__device__ __align__(16) __half g_kf[(size_t)B_ * S_ * GROW];
__device__ __align__(16) __half g_vf[(size_t)B_ * S_ * GROW];
__device__ float g_rowsum[(size_t)B_ * S_];

static __device__ __forceinline__ uint32_t smem_u32(const void* p) {
    uint32_t a;
    asm("{ .reg .u64 t; cvta.to.shared.u64 t, %1; cvt.u32.u64 %0, t; }" : "=r"(a) : "l"(p));
    return a;
}
static __device__ __forceinline__ void ldsm4(uint32_t* r, uint32_t addr) {
    asm volatile("ldmatrix.sync.aligned.m8n8.x4.shared.b16 {%0,%1,%2,%3}, [%4];"
                 : "=r"(r[0]), "=r"(r[1]), "=r"(r[2]), "=r"(r[3]) : "r"(addr));
}
static __device__ __forceinline__ void ldsm4t(uint32_t* r, uint32_t addr) {
    asm volatile("ldmatrix.sync.aligned.m8n8.x4.trans.shared.b16 {%0,%1,%2,%3}, [%4];"
                 : "=r"(r[0]), "=r"(r[1]), "=r"(r[2]), "=r"(r[3]) : "r"(addr));
}
static __device__ __forceinline__ void mma_f16(float* c, const uint32_t* a,
                                               uint32_t b0, uint32_t b1) {
    asm volatile("mma.sync.aligned.m16n8k16.row.col.f32.f16.f16.f32 "
                 "{%0,%1,%2,%3}, {%4,%5,%6,%7}, {%8,%9}, {%0,%1,%2,%3};"
                 : "+f"(c[0]), "+f"(c[1]), "+f"(c[2]), "+f"(c[3])
                 : "r"(a[0]), "r"(a[1]), "r"(a[2]), "r"(a[3]), "r"(b0), "r"(b1));
}
static __device__ __forceinline__ uint32_t packhf(float a, float b) {
    __half2 t = __floats2half2_rn(a, b);
    return *reinterpret_cast<uint32_t*>(&t);
}

// ---- one-time convert of K/V to fp16 in tile-ready layout ----
__global__ __launch_bounds__(256)
void prep_half_kernel(const float* __restrict__ K, const float* __restrict__ V)
{
    size_t idx = (size_t)blockIdx.x * 256 + threadIdx.x;   // float4 index
    size_t row = idx >> 4;
    int d4 = (int)(idx & 15);
    size_t dst = row * GROW + (size_t)d4 * 4;

    float4 kv = reinterpret_cast<const float4*>(K)[idx];
    *reinterpret_cast<uint2*>(&g_kf[dst]) =
        make_uint2(packhf(kv.x, kv.y), packhf(kv.z, kv.w));
    float4 vv = reinterpret_cast<const float4*>(V)[idx];
    *reinterpret_cast<uint2*>(&g_vf[dst]) =
        make_uint2(packhf(vv.x, vv.y), packhf(vv.z, vv.w));
}

__global__ __launch_bounds__(NTH, 2)
void attn_hmma_kernel(const float* __restrict__ Q,
                      const int*   __restrict__ mask,
                      float* __restrict__ ctx_out,
                      float* __restrict__ attn_out)
{
    extern __shared__ char smc[];
    const uint32_t sb = smem_u32(smc);

    const int tid  = threadIdx.x;
    const int w    = tid >> 5;          // warp owns q-rows [16w, 16w+16)
    const int lane = tid & 31;
    const int lrow = lane & 7;
    const int lsub = lane >> 3;
    const int b    = blockIdx.y;
    const int q0   = blockIdx.x * BQ;

    const uint32_t kofsB = (uint32_t)((((lsub & 2) ? 8 : 0) + lrow) * 144 + ((lsub & 1) ? 16 : 0));
    const uint32_t kofsV = (uint32_t)((lrow + ((lsub & 1) ? 8 : 0)) * 144 + ((lsub & 2) ? 16 : 0));

    // async copy of one k-tile (KF + VF, each 1152 x 16B) into a stage
    auto issue_copy = [&](int t, int stg) {
        size_t gbase = ((size_t)b * S_ + (size_t)t * BK) * GROW;
        const __half* gp[2] = { g_kf + gbase, g_vf + gbase };
        uint32_t s0 = sb + (uint32_t)stg * STAGE_BYTES;
        #pragma unroll
        for (int a = 0; a < 2; ++a) {
            uint64_t ga = (uint64_t)__cvta_generic_to_global(gp[a]);
            uint32_t sa = s0 + (uint32_t)a * 18432u;
            #pragma unroll
            for (int i = 0; i < 4; ++i) {
                uint32_t o = (uint32_t)(tid + i * NTH) * 16u;
                asm volatile("cp.async.cg.shared.global [%0], [%1], 16;"
                             :: "r"(sa + o), "l"(ga + o));
            }
            if (tid < 128) {
                uint32_t o = (uint32_t)(1024 + tid) * 16u;
                asm volatile("cp.async.cg.shared.global [%0], [%1], 16;"
                             :: "r"(sa + o), "l"(ga + o));
            }
        }
        asm volatile("cp.async.commit_group;" ::: "memory");
    };

    // prologue: tiles 0,1 in flight; Q (scaled 1/8) staged in stage-2 slot
    issue_copy(0, 0);
    issue_copy(1, 1);
    {
        float* smf = reinterpret_cast<float*>(smc + 2 * STAGE_BYTES);
        const float* Qg = Q + ((size_t)b * S_ + q0) * D_HD;
        #pragma unroll
        for (int it = 0; it < 8; ++it) {
            int idx = (it * NTH + tid) * 4;
            int q = idx >> 6, d = idx & 63;
            float4 v = *reinterpret_cast<const float4*>(Qg + idx);
            float* dst = smf + q * QS_STRIDE + d;
            dst[0] = v.x * 0.125f; dst[1] = v.y * 0.125f;
            dst[2] = v.z * 0.125f; dst[3] = v.w * 0.125f;
        }
    }
    __syncthreads();

    // persistent fp16 Q A-fragments (16 regs)
    uint32_t qf[4][4];
    {
        const float* smf = reinterpret_cast<const float*>(smc + 2 * STAGE_BYTES);
        const int r0 = 16 * w + (lane >> 2);
        const int c0 = 2 * (lane & 3);
        #pragma unroll
        for (int kc = 0; kc < 4; ++kc) {
            #pragma unroll
            for (int f = 0; f < 4; ++f) {
                int rr = r0 + ((f & 1) ? 8 : 0);
                int cc = kc * 16 + c0 + ((f & 2) ? 8 : 0);
                float2 v = *reinterpret_cast<const float2*>(smf + rr * QS_STRIDE + cc);
                qf[kc][f] = packhf(v.x, v.y);
            }
        }
    }
    __syncthreads();   // Q staging done; stage-2 free for the pipeline

    float ctx[8][4];
    #pragma unroll
    for (int i = 0; i < 8; ++i)
        #pragma unroll
        for (int j = 0; j < 4; ++j) ctx[i][j] = 0.0f;
    float rs0 = 0.0f, rs1 = 0.0f;

    const size_t rowA = (size_t)b * S_ + q0 + 16 * w + (lane >> 2);
    const int    colL = 2 * (lane & 3);

    for (int t = 0; t < S_ / BK; ++t) {
        const int k0 = t << 7;

        if (t < S_ / BK - 1)
            asm volatile("cp.async.wait_group 1;" ::: "memory");
        else
            asm volatile("cp.async.wait_group 0;" ::: "memory");
        __syncthreads();                        // tile t resident, stage (t+2)%3 free
        if (t + 2 < S_ / BK) issue_copy(t + 2, (t + 2) % 3);

        const uint32_t base = sb + (uint32_t)(t % 3) * STAGE_BYTES;

        #pragma unroll
        for (int h = 0; h < 2; ++h) {
            // ---- QK^T half: single-pass fp16 ----
            float sc[8][4];
            #pragma unroll
            for (int i = 0; i < 8; ++i)
                #pragma unroll
                for (int j = 0; j < 4; ++j) sc[i][j] = 0.0f;

            const uint32_t bbase = base + OFF_KF + (uint32_t)(h * 9216) + kofsB;
            #pragma unroll
            for (int kc = 0; kc < 4; ++kc) {
                #pragma unroll
                for (int ntp = 0; ntp < 4; ++ntp) {
                    uint32_t bfr[4];
                    ldsm4(bfr, bbase + (uint32_t)(ntp * 2304 + kc * 32));
                    mma_f16(sc[2 * ntp],     qf[kc], bfr[0], bfr[1]);
                    mma_f16(sc[2 * ntp + 1], qf[kc], bfr[2], bfr[3]);
                }
            }

            // ---- mask + exp + direct attn write ----
            #pragma unroll
            for (int nt = 0; nt < 8; ++nt) {
                const size_t cg = (size_t)(k0 + h * 64 + nt * 8 + colL);
                const int2 m0 = *reinterpret_cast<const int2*>(mask + rowA * S_ + cg);
                const int2 m1 = *reinterpret_cast<const int2*>(mask + (rowA + 8) * S_ + cg);
                float e0 = m0.x ? 0.0f : __expf(sc[nt][0]);
                float e1 = m0.y ? 0.0f : __expf(sc[nt][1]);
                float e2 = m1.x ? 0.0f : __expf(sc[nt][2]);
                float e3 = m1.y ? 0.0f : __expf(sc[nt][3]);
                rs0 += e0 + e1; rs1 += e2 + e3;
                *reinterpret_cast<float2*>(attn_out + rowA * S_ + cg)       = make_float2(e0, e1);
                *reinterpret_cast<float2*>(attn_out + (rowA + 8) * S_ + cg) = make_float2(e2, e3);
                sc[nt][0] = e0; sc[nt][1] = e1; sc[nt][2] = e2; sc[nt][3] = e3;
            }

            // ---- repack P to fp16 A-fragments (C-layout == A-layout) ----
            uint32_t pf[4][4];
            #pragma unroll
            for (int kcp = 0; kcp < 4; ++kcp) {
                #pragma unroll
                for (int f = 0; f < 4; ++f) {
                    const float* s = sc[2 * kcp + ((f & 2) ? 1 : 0)];
                    pf[kcp][f] = packhf(s[(f & 1) ? 2 : 0], s[(f & 1) ? 3 : 1]);
                }
            }

            // ---- P·V half: single-pass fp16, k-slice h ----
            const uint32_t vbase = base + OFF_VF + (uint32_t)(h * 9216) + kofsV;
            #pragma unroll
            for (int kcp = 0; kcp < 4; ++kcp) {
                #pragma unroll
                for (int ntp = 0; ntp < 4; ++ntp) {
                    uint32_t vf[4];
                    ldsm4t(vf, vbase + (uint32_t)(kcp * 2304 + ntp * 32));
                    mma_f16(ctx[2 * ntp],     pf[kcp], vf[0], vf[1]);
                    mma_f16(ctx[2 * ntp + 1], pf[kcp], vf[2], vf[3]);
                }
            }
        }
    }

    // ---- rowsums + normalized ctx ----
    rs0 += __shfl_xor_sync(0xffffffffu, rs0, 1);
    rs0 += __shfl_xor_sync(0xffffffffu, rs0, 2);
    rs1 += __shfl_xor_sync(0xffffffffu, rs1, 1);
    rs1 += __shfl_xor_sync(0xffffffffu, rs1, 2);
    __syncthreads();
    float* rsum = reinterpret_cast<float*>(smc + SM_RS);
    if ((lane & 3) == 0) {
        rsum[16 * w + (lane >> 2)]     = rs0;
        rsum[16 * w + (lane >> 2) + 8] = rs1;
    }
    __syncthreads();
    if (tid < BQ) g_rowsum[(size_t)b * S_ + q0 + tid] = rsum[tid];

    const float inv0 = 1.0f / rsum[16 * w + (lane >> 2)];
    const float inv1 = 1.0f / rsum[16 * w + (lane >> 2) + 8];
    #pragma unroll
    for (int nt = 0; nt < 8; ++nt) {
        int d = nt * 8 + colL;
        *reinterpret_cast<float2*>(ctx_out + rowA * D_HD + d) =
            make_float2(ctx[nt][0] * inv0, ctx[nt][1] * inv0);
        *reinterpret_cast<float2*>(ctx_out + (rowA + 8) * D_HD + d) =
            make_float2(ctx[nt][2] * inv1, ctx[nt][3] * inv1);
    }
}

__global__ void attn_norm_kernel(float* __restrict__ attn)
{
    const size_t n4 = (size_t)B_ * S_ * S_ / 4;
    for (size_t i = (size_t)blockIdx.x * blockDim.x + threadIdx.x;
         i < n4; i += (size_t)gridDim.x * blockDim.x) {
        float4 v = reinterpret_cast<const float4*>(attn)[i];
        size_t row = i >> 10;
        float s = __fdividef(1.0f, g_rowsum[row]);
        v.x *= s; v.y *= s; v.z *= s; v.w *= s;
        reinterpret_cast<float4*>(attn)[i] = v;
    }
}

extern "C" void kernel_launch(void* const* d_in, const int* in_sizes, int n_in,
                              void* d_out, int out_size)
{
    const float* Q = (const float*)d_in[0];
    const float* K = (const float*)d_in[1];
    const float* V = (const float*)d_in[2];
    const int* mask = (const int*)d_in[3];

    float* ctx_out  = (float*)d_out;
    float* attn_out = ctx_out + (size_t)B_ * S_ * D_HD;

    static bool attr_set = false;
    if (!attr_set) {
        cudaFuncSetAttribute(attn_hmma_kernel,
                             cudaFuncAttributeMaxDynamicSharedMemorySize, SM_TOT);
        attr_set = true;
    }

    prep_half_kernel<<<(B_ * S_ * D_HD / 4) / 256, 256>>>(K, V);
    dim3 grid(S_ / BQ, B_);
    attn_hmma_kernel<<<grid, NTH, SM_TOT>>>(Q, mask, ctx_out, attn_out);
    attn_norm_kernel<<<8192, 256>>>(attn_out);
}